// round 4
// baseline (speedup 1.0000x reference)
#include <cuda_runtime.h>

#define IN_F   4096
#define OUT_F  11008
#define NC     16
#define TOPK   1024

__device__ float g_xmask[IN_F];
__device__ float g_d2[NC];

// ---------------------------------------------------------------------------
// Kernel 1: one block per center, 1024 threads. Each block redundantly
// computes softmax(|x|) (identical, deterministic) then d2 to its center.
// ---------------------------------------------------------------------------
__global__ void __launch_bounds__(1024)
distc_kernel(const float* __restrict__ x,
             const float* __restrict__ centers)
{
    __shared__ float s_red[32];
    __shared__ float s_b;

    const int tid  = threadIdx.x;
    const int lane = tid & 31;
    const int wid  = tid >> 5;
    const int c    = blockIdx.x;

    // |x|, block max
    const float4 xv = reinterpret_cast<const float4*>(x)[tid];
    float a[4] = { fabsf(xv.x), fabsf(xv.y), fabsf(xv.z), fabsf(xv.w) };
    float m = fmaxf(fmaxf(a[0], a[1]), fmaxf(a[2], a[3]));
#pragma unroll
    for (int o = 16; o > 0; o >>= 1) m = fmaxf(m, __shfl_xor_sync(0xffffffffu, m, o));
    if (lane == 0) s_red[wid] = m;
    __syncthreads();
    if (tid == 0) {
        float r = s_red[0];
#pragma unroll
        for (int w = 1; w < 32; w++) r = fmaxf(r, s_red[w]);
        s_b = r;
    }
    __syncthreads();
    m = s_b;
    __syncthreads();

    // exp + sum
    float e[4];
    float s = 0.f;
#pragma unroll
    for (int k = 0; k < 4; k++) { e[k] = expf(a[k] - m); s += e[k]; }
#pragma unroll
    for (int o = 16; o > 0; o >>= 1) s += __shfl_xor_sync(0xffffffffu, s, o);
    if (lane == 0) s_red[wid] = s;
    __syncthreads();
    if (tid == 0) {
        float r = 0.f;
#pragma unroll
        for (int w = 0; w < 32; w++) r += s_red[w];
        s_b = r;
    }
    __syncthreads();
    const float inv_s = 1.f / s_b;
    __syncthreads();

    // squared distance to center c
    const float4 cv = reinterpret_cast<const float4*>(centers)[c * (IN_F / 4) + tid];
    float dx = cv.x - e[0] * inv_s;
    float dy = cv.y - e[1] * inv_s;
    float dz = cv.z - e[2] * inv_s;
    float dw = cv.w - e[3] * inv_s;
    float d2 = dx * dx + dy * dy + dz * dz + dw * dw;
#pragma unroll
    for (int o = 16; o > 0; o >>= 1) d2 += __shfl_xor_sync(0xffffffffu, d2, o);
    if (lane == 0) s_red[wid] = d2;
    __syncthreads();
    if (tid == 0) {
        float r = 0.f;
#pragma unroll
        for (int w = 0; w < 32; w++) r += s_red[w];
        g_d2[c] = r;
    }
}

// ---------------------------------------------------------------------------
// Kernel 2: argmin over g_d2, exact top-1024 radix select on chosen center,
// write masked x. Single block, 1024 threads.
// ---------------------------------------------------------------------------
__global__ void __launch_bounds__(1024)
select_kernel(const float* __restrict__ x,
              const float* __restrict__ centers)
{
    __shared__ unsigned s_keys[IN_F];
    __shared__ unsigned s_hist[4][256];
    __shared__ unsigned s_wsum[8];
    __shared__ int      s_ints[3];   // [0]=ci [1]=remaining [2]=prefix
    __shared__ int      s_warp[32];

    const int tid  = threadIdx.x;
    const int lane = tid & 31;
    const int wid  = tid >> 5;
    const int base = tid * 4;

    ((unsigned*)s_hist)[tid] = 0u;   // clear all 4 histograms (1 entry/thread)

    if (tid == 0) {
        int best = 0;
        float bv = g_d2[0];
        for (int c = 1; c < NC; c++)
            if (g_d2[c] < bv) { bv = g_d2[c]; best = c; }   // first-min tie-break
        s_ints[0] = best;
    }
    const float4 xv4 = reinterpret_cast<const float4*>(x)[tid];
    __syncthreads();

    // keys = bits of chosen center (positive floats -> monotone uint)
    {
        const int ci = s_ints[0];
        const float4 cv = reinterpret_cast<const float4*>(centers)[ci * (IN_F / 4) + tid];
        s_keys[base + 0] = __float_as_uint(cv.x);
        s_keys[base + 1] = __float_as_uint(cv.y);
        s_keys[base + 2] = __float_as_uint(cv.z);
        s_keys[base + 3] = __float_as_uint(cv.w);
    }
    __syncthreads();

    // radix-select threshold T = TOPK-th largest key
    unsigned prefix    = 0;
    int      remaining = TOPK;
#pragma unroll
    for (int p = 0; p < 4; p++) {
        const int shift = 24 - 8 * p;
#pragma unroll
        for (int j = 0; j < 4; j++) {
            unsigned key = s_keys[base + j];
            bool match = (p == 0) ||
                         ((key >> (shift + 8)) == (prefix >> (shift + 8)));
            if (match) atomicAdd(&s_hist[p][(key >> shift) & 255u], 1u);
        }
        __syncthreads();
        unsigned v = 0, cnt = 0;
        if (tid < 256) {
            cnt = s_hist[p][tid];
            v = cnt;
#pragma unroll
            for (int off = 1; off < 32; off <<= 1) {
                unsigned n = __shfl_down_sync(0xffffffffu, v, off);
                if (lane + off < 32) v += n;
            }
            if (lane == 0) s_wsum[wid] = v;
        }
        __syncthreads();
        if (tid < 256) {
            unsigned off = 0;
            for (int w2 = wid + 1; w2 < 8; w2++) off += s_wsum[w2];
            unsigned ge = v + off;           // #keys with byte >= tid (among matching)
            unsigned gt = ge - cnt;          // #keys with byte >  tid
            if ((int)ge >= remaining && (int)gt < remaining) {   // unique crossing bin
                s_ints[1] = remaining - (int)gt;
                s_ints[2] = (int)(prefix | ((unsigned)tid << shift));
            }
        }
        __syncthreads();
        remaining = s_ints[1];
        prefix    = (unsigned)s_ints[2];
        __syncthreads();
    }
    const unsigned T = prefix;
    const int      R = remaining;   // take the R lowest-index ties (jax top_k order)

    // tie-rank prefix scan (index order) + write masked x
    int cnt4[4];
    int tot = 0;
#pragma unroll
    for (int j = 0; j < 4; j++) {
        cnt4[j] = tot;
        tot += (s_keys[base + j] == T) ? 1 : 0;
    }
    int incl = tot;
#pragma unroll
    for (int off = 1; off < 32; off <<= 1) {
        int n = __shfl_up_sync(0xffffffffu, incl, off);
        if (lane >= off) incl += n;
    }
    if (lane == 31) s_warp[wid] = incl;
    __syncthreads();
    if (wid == 0) {
        int v = s_warp[lane];
#pragma unroll
        for (int off = 1; off < 32; off <<= 1) {
            int n = __shfl_up_sync(0xffffffffu, v, off);
            if (lane >= off) v += n;
        }
        s_warp[lane] = v;
    }
    __syncthreads();
    const int excl = incl - tot + (wid > 0 ? s_warp[wid - 1] : 0);
    const float xin[4] = { xv4.x, xv4.y, xv4.z, xv4.w };
    float o4[4];
#pragma unroll
    for (int j = 0; j < 4; j++) {
        unsigned key = s_keys[base + j];
        bool sel = (key > T) || (key == T && (excl + cnt4[j]) < R);
        o4[j] = sel ? xin[j] : 0.f;
    }
    reinterpret_cast<float4*>(g_xmask)[tid] = make_float4(o4[0], o4[1], o4[2], o4[3]);
}

// ---------------------------------------------------------------------------
// Kernel 3: out = W @ x_masked + bias   (HBM-streaming dense matvec)
// 256 threads = 8 warps, 1 row/warp, grid=1376, forced 8 blocks/SM.
// ---------------------------------------------------------------------------
__global__ void __launch_bounds__(256, 8)
matvec_kernel(const float* __restrict__ W,
              const float* __restrict__ bias,
              float* __restrict__ out)
{
    __shared__ float4 sx[IN_F / 4];
    const int tid = threadIdx.x;
    for (int i = tid; i < IN_F / 4; i += 256)
        sx[i] = reinterpret_cast<const float4*>(g_xmask)[i];
    __syncthreads();

    const int warp = tid >> 5;
    const int lane = tid & 31;
    const int row  = blockIdx.x * 8 + warp;   // 11008 = 1376 * 8, always in range

    const float4* wr = reinterpret_cast<const float4*>(W + (size_t)row * IN_F);
    const float b = bias[row];

    float acc = 0.f;
#pragma unroll 8
    for (int j = lane; j < IN_F / 4; j += 32) {
        float4 w  = wr[j];
        float4 xv = sx[j];
        acc += w.x * xv.x + w.y * xv.y + w.z * xv.z + w.w * xv.w;
    }
#pragma unroll
    for (int o = 16; o > 0; o >>= 1)
        acc += __shfl_xor_sync(0xffffffffu, acc, o);
    if (lane == 0)
        out[row] = acc + b;
}

// ---------------------------------------------------------------------------
extern "C" void kernel_launch(void* const* d_in, const int* in_sizes, int n_in,
                              void* d_out, int out_size)
{
    const float* x       = (const float*)d_in[0];  // [4096]
    const float* weight  = (const float*)d_in[1];  // [11008, 4096]
    const float* bias    = (const float*)d_in[2];  // [11008]
    const float* centers = (const float*)d_in[3];  // [16, 4096]
    float*       out     = (float*)d_out;          // [11008]

    distc_kernel<<<NC, 1024>>>(x, centers);
    select_kernel<<<1, 1024>>>(x, centers);
    matvec_kernel<<<OUT_F / 8, 256>>>(weight, bias, out);
}

// round 5
// speedup vs baseline: 1.0139x; 1.0139x over previous
#include <cuda_runtime.h>

#define IN_F   4096
#define OUT_F  11008
#define NC     16
#define TOPK   1024

__device__ float g_xmask[IN_F];
__device__ float g_d2[NC];

// ---------------------------------------------------------------------------
// Kernel 1: one block per center, 1024 threads. Each block redundantly
// computes softmax(|x|) (identical, deterministic) then d2 to its center.
// Center row is prefetched at entry so both DRAM latencies overlap.
// ---------------------------------------------------------------------------
__global__ void __launch_bounds__(1024)
distc_kernel(const float* __restrict__ x,
             const float* __restrict__ centers)
{
    __shared__ float s_red[32];
    __shared__ float s_b;

    const int tid  = threadIdx.x;
    const int lane = tid & 31;
    const int wid  = tid >> 5;
    const int c    = blockIdx.x;

    // issue BOTH loads up front (independent) — overlap the two DRAM trips
    const float4 xv = reinterpret_cast<const float4*>(x)[tid];
    const float4 cv = reinterpret_cast<const float4*>(centers)[c * (IN_F / 4) + tid];

    // |x|, block max
    float a[4] = { fabsf(xv.x), fabsf(xv.y), fabsf(xv.z), fabsf(xv.w) };
    float m = fmaxf(fmaxf(a[0], a[1]), fmaxf(a[2], a[3]));
#pragma unroll
    for (int o = 16; o > 0; o >>= 1) m = fmaxf(m, __shfl_xor_sync(0xffffffffu, m, o));
    if (lane == 0) s_red[wid] = m;
    __syncthreads();
    if (wid == 0) {
        float r = s_red[lane];
#pragma unroll
        for (int o = 16; o > 0; o >>= 1) r = fmaxf(r, __shfl_xor_sync(0xffffffffu, r, o));
        if (lane == 0) s_b = r;
    }
    __syncthreads();
    m = s_b;
    __syncthreads();

    // exp + sum
    float e[4];
    float s = 0.f;
#pragma unroll
    for (int k = 0; k < 4; k++) { e[k] = expf(a[k] - m); s += e[k]; }
#pragma unroll
    for (int o = 16; o > 0; o >>= 1) s += __shfl_xor_sync(0xffffffffu, s, o);
    if (lane == 0) s_red[wid] = s;
    __syncthreads();
    if (wid == 0) {
        float r = s_red[lane];
#pragma unroll
        for (int o = 16; o > 0; o >>= 1) r += __shfl_xor_sync(0xffffffffu, r, o);
        if (lane == 0) s_b = r;
    }
    __syncthreads();
    const float inv_s = 1.f / s_b;

    // squared distance to center c (cv already in registers)
    float dx = cv.x - e[0] * inv_s;
    float dy = cv.y - e[1] * inv_s;
    float dz = cv.z - e[2] * inv_s;
    float dw = cv.w - e[3] * inv_s;
    float d2 = dx * dx + dy * dy + dz * dz + dw * dw;
#pragma unroll
    for (int o = 16; o > 0; o >>= 1) d2 += __shfl_xor_sync(0xffffffffu, d2, o);
    __syncthreads();           // s_red reuse safe
    if (lane == 0) s_red[wid] = d2;
    __syncthreads();
    if (wid == 0) {
        float r = s_red[lane];
#pragma unroll
        for (int o = 16; o > 0; o >>= 1) r += __shfl_xor_sync(0xffffffffu, r, o);
        if (lane == 0) g_d2[c] = r;
    }
}

// ---------------------------------------------------------------------------
// Kernel 2: argmin over g_d2, exact top-1024 radix select on chosen center,
// write masked x. Single block, 1024 threads.
// ---------------------------------------------------------------------------
__global__ void __launch_bounds__(1024)
select_kernel(const float* __restrict__ x,
              const float* __restrict__ centers)
{
    __shared__ unsigned s_keys[IN_F];
    __shared__ unsigned s_hist[4][256];
    __shared__ unsigned s_wsum[8];
    __shared__ int      s_ints[3];   // [0]=ci [1]=remaining [2]=prefix
    __shared__ int      s_warp[32];

    const int tid  = threadIdx.x;
    const int lane = tid & 31;
    const int wid  = tid >> 5;
    const int base = tid * 4;

    ((unsigned*)s_hist)[tid] = 0u;   // clear all 4 histograms (1 entry/thread)

    if (tid == 0) {
        int best = 0;
        float bv = g_d2[0];
        for (int c = 1; c < NC; c++)
            if (g_d2[c] < bv) { bv = g_d2[c]; best = c; }   // first-min tie-break
        s_ints[0] = best;
    }
    const float4 xv4 = reinterpret_cast<const float4*>(x)[tid];
    __syncthreads();

    // keys = bits of chosen center (positive floats -> monotone uint)
    {
        const int ci = s_ints[0];
        const float4 cv = reinterpret_cast<const float4*>(centers)[ci * (IN_F / 4) + tid];
        s_keys[base + 0] = __float_as_uint(cv.x);
        s_keys[base + 1] = __float_as_uint(cv.y);
        s_keys[base + 2] = __float_as_uint(cv.z);
        s_keys[base + 3] = __float_as_uint(cv.w);
    }
    __syncthreads();

    // radix-select threshold T = TOPK-th largest key
    unsigned prefix    = 0;
    int      remaining = TOPK;
#pragma unroll
    for (int p = 0; p < 4; p++) {
        const int shift = 24 - 8 * p;
#pragma unroll
        for (int j = 0; j < 4; j++) {
            unsigned key = s_keys[base + j];
            bool match = (p == 0) ||
                         ((key >> (shift + 8)) == (prefix >> (shift + 8)));
            if (match) atomicAdd(&s_hist[p][(key >> shift) & 255u], 1u);
        }
        __syncthreads();
        unsigned v = 0, cnt = 0;
        if (tid < 256) {
            cnt = s_hist[p][tid];
            v = cnt;
#pragma unroll
            for (int off = 1; off < 32; off <<= 1) {
                unsigned n = __shfl_down_sync(0xffffffffu, v, off);
                if (lane + off < 32) v += n;
            }
            if (lane == 0) s_wsum[wid] = v;
        }
        __syncthreads();
        if (tid < 256) {
            unsigned off = 0;
            for (int w2 = wid + 1; w2 < 8; w2++) off += s_wsum[w2];
            unsigned ge = v + off;           // #keys with byte >= tid (among matching)
            unsigned gt = ge - cnt;          // #keys with byte >  tid
            if ((int)ge >= remaining && (int)gt < remaining) {   // unique crossing bin
                s_ints[1] = remaining - (int)gt;
                s_ints[2] = (int)(prefix | ((unsigned)tid << shift));
            }
        }
        __syncthreads();
        remaining = s_ints[1];
        prefix    = (unsigned)s_ints[2];
        __syncthreads();
    }
    const unsigned T = prefix;
    const int      R = remaining;   // take the R lowest-index ties (jax top_k order)

    // tie-rank prefix scan (index order) + write masked x
    int cnt4[4];
    int tot = 0;
#pragma unroll
    for (int j = 0; j < 4; j++) {
        cnt4[j] = tot;
        tot += (s_keys[base + j] == T) ? 1 : 0;
    }
    int incl = tot;
#pragma unroll
    for (int off = 1; off < 32; off <<= 1) {
        int n = __shfl_up_sync(0xffffffffu, incl, off);
        if (lane >= off) incl += n;
    }
    if (lane == 31) s_warp[wid] = incl;
    __syncthreads();
    if (wid == 0) {
        int v = s_warp[lane];
#pragma unroll
        for (int off = 1; off < 32; off <<= 1) {
            int n = __shfl_up_sync(0xffffffffu, v, off);
            if (lane >= off) v += n;
        }
        s_warp[lane] = v;
    }
    __syncthreads();
    const int excl = incl - tot + (wid > 0 ? s_warp[wid - 1] : 0);
    const float xin[4] = { xv4.x, xv4.y, xv4.z, xv4.w };
    float o4[4];
#pragma unroll
    for (int j = 0; j < 4; j++) {
        unsigned key = s_keys[base + j];
        bool sel = (key > T) || (key == T && (excl + cnt4[j]) < R);
        o4[j] = sel ? xin[j] : 0.f;
    }
    reinterpret_cast<float4*>(g_xmask)[tid] = make_float4(o4[0], o4[1], o4[2], o4[3]);
}

// ---------------------------------------------------------------------------
// Kernel 3: out = W @ x_masked + bias   (HBM-streaming dense matvec)
// block=128 (4 warps, 4 rows/block), grid=2752. Natural regs (no min-blocks
// clause!), dual same-row accumulator streams. ~12 blocks/SM -> 75% occ cap.
// ---------------------------------------------------------------------------
__global__ void __launch_bounds__(128)
matvec_kernel(const float* __restrict__ W,
              const float* __restrict__ bias,
              float* __restrict__ out)
{
    __shared__ float4 sx[IN_F / 4];
    const int tid = threadIdx.x;
    for (int i = tid; i < IN_F / 4; i += 128)
        sx[i] = reinterpret_cast<const float4*>(g_xmask)[i];
    __syncthreads();

    const int warp = tid >> 5;
    const int lane = tid & 31;
    const int row  = blockIdx.x * 4 + warp;   // 11008 = 2752 * 4, always in range

    const float4* wr = reinterpret_cast<const float4*>(W + (size_t)row * IN_F);

    float acc0 = 0.f, acc1 = 0.f;
#pragma unroll 4
    for (int j = lane; j < IN_F / 4; j += 64) {
        float4 wa = wr[j];
        float4 wb = wr[j + 32];
        float4 xa = sx[j];
        float4 xb = sx[j + 32];
        acc0 += wa.x * xa.x + wa.y * xa.y + wa.z * xa.z + wa.w * xa.w;
        acc1 += wb.x * xb.x + wb.y * xb.y + wb.z * xb.z + wb.w * xb.w;
    }
    float acc = acc0 + acc1;
#pragma unroll
    for (int o = 16; o > 0; o >>= 1)
        acc += __shfl_xor_sync(0xffffffffu, acc, o);
    if (lane == 0)
        out[row] = acc + bias[row];
}

// ---------------------------------------------------------------------------
extern "C" void kernel_launch(void* const* d_in, const int* in_sizes, int n_in,
                              void* d_out, int out_size)
{
    const float* x       = (const float*)d_in[0];  // [4096]
    const float* weight  = (const float*)d_in[1];  // [11008, 4096]
    const float* bias    = (const float*)d_in[2];  // [11008]
    const float* centers = (const float*)d_in[3];  // [16, 4096]
    float*       out     = (float*)d_out;          // [11008]

    distc_kernel<<<NC, 1024>>>(x, centers);
    select_kernel<<<1, 1024>>>(x, centers);
    matvec_kernel<<<OUT_F / 4, 128>>>(weight, bias, out);
}

// round 6
// speedup vs baseline: 1.0734x; 1.0587x over previous
#include <cuda_runtime.h>

#define IN_F   4096
#define OUT_F  11008
#define NC     16
#define TOPK   1024

__device__ float g_xmask[IN_F];
__device__ float g_act[IN_F];
__device__ float g_d2[NC];

// ---------------------------------------------------------------------------
// Kernel 1: softmax(|x|) -> g_act. One block, 1024 threads.
// ---------------------------------------------------------------------------
__global__ void __launch_bounds__(1024)
softmax_kernel(const float* __restrict__ x)
{
    __shared__ float s_red[32];
    __shared__ float s_b;

    const int tid  = threadIdx.x;
    const int lane = tid & 31;
    const int wid  = tid >> 5;

    const float4 xv = reinterpret_cast<const float4*>(x)[tid];
    float a[4] = { fabsf(xv.x), fabsf(xv.y), fabsf(xv.z), fabsf(xv.w) };
    float m = fmaxf(fmaxf(a[0], a[1]), fmaxf(a[2], a[3]));
#pragma unroll
    for (int o = 16; o > 0; o >>= 1) m = fmaxf(m, __shfl_xor_sync(0xffffffffu, m, o));
    if (lane == 0) s_red[wid] = m;
    __syncthreads();
    if (wid == 0) {
        float r = s_red[lane];
#pragma unroll
        for (int o = 16; o > 0; o >>= 1) r = fmaxf(r, __shfl_xor_sync(0xffffffffu, r, o));
        if (lane == 0) s_b = r;
    }
    __syncthreads();
    m = s_b;
    __syncthreads();

    float e[4];
    float s = 0.f;
#pragma unroll
    for (int k = 0; k < 4; k++) { e[k] = expf(a[k] - m); s += e[k]; }
#pragma unroll
    for (int o = 16; o > 0; o >>= 1) s += __shfl_xor_sync(0xffffffffu, s, o);
    if (lane == 0) s_red[wid] = s;
    __syncthreads();
    if (wid == 0) {
        float r = s_red[lane];
#pragma unroll
        for (int o = 16; o > 0; o >>= 1) r += __shfl_xor_sync(0xffffffffu, r, o);
        if (lane == 0) s_b = r;
    }
    __syncthreads();
    const float inv_s = 1.f / s_b;
    reinterpret_cast<float4*>(g_act)[tid] =
        make_float4(e[0] * inv_s, e[1] * inv_s, e[2] * inv_s, e[3] * inv_s);
}

// ---------------------------------------------------------------------------
// Kernel 2: one block per center, 1024 threads. d2 to g_act (L2-hot).
// Center load (DRAM) and act load (L2) issued together.
// ---------------------------------------------------------------------------
__global__ void __launch_bounds__(1024)
dist_kernel(const float* __restrict__ centers)
{
    __shared__ float s_red[32];

    const int tid  = threadIdx.x;
    const int lane = tid & 31;
    const int wid  = tid >> 5;
    const int c    = blockIdx.x;

    const float4 cv = reinterpret_cast<const float4*>(centers)[c * (IN_F / 4) + tid];
    const float4 av = reinterpret_cast<const float4*>(g_act)[tid];

    float dx = cv.x - av.x, dy = cv.y - av.y;
    float dz = cv.z - av.z, dw = cv.w - av.w;
    float d2 = dx * dx + dy * dy + dz * dz + dw * dw;
#pragma unroll
    for (int o = 16; o > 0; o >>= 1) d2 += __shfl_xor_sync(0xffffffffu, d2, o);
    if (lane == 0) s_red[wid] = d2;
    __syncthreads();
    if (wid == 0) {
        float r = s_red[lane];
#pragma unroll
        for (int o = 16; o > 0; o >>= 1) r += __shfl_xor_sync(0xffffffffu, r, o);
        if (lane == 0) g_d2[c] = r;
    }
}

// ---------------------------------------------------------------------------
// Kernel 3: argmin over g_d2, exact top-1024 radix select on chosen center,
// write masked x. Single block, 1024 threads.
// ---------------------------------------------------------------------------
__global__ void __launch_bounds__(1024)
select_kernel(const float* __restrict__ x,
              const float* __restrict__ centers)
{
    __shared__ unsigned s_keys[IN_F];
    __shared__ unsigned s_hist[4][256];
    __shared__ unsigned s_wsum[8];
    __shared__ int      s_ints[3];   // [0]=ci [1]=remaining [2]=prefix
    __shared__ int      s_warp[32];

    const int tid  = threadIdx.x;
    const int lane = tid & 31;
    const int wid  = tid >> 5;
    const int base = tid * 4;

    ((unsigned*)s_hist)[tid] = 0u;   // clear all 4 histograms (1 entry/thread)

    if (tid == 0) {
        int best = 0;
        float bv = g_d2[0];
        for (int c = 1; c < NC; c++)
            if (g_d2[c] < bv) { bv = g_d2[c]; best = c; }   // first-min tie-break
        s_ints[0] = best;
    }
    const float4 xv4 = reinterpret_cast<const float4*>(x)[tid];
    __syncthreads();

    // keys = bits of chosen center (positive floats -> monotone uint)
    {
        const int ci = s_ints[0];
        const float4 cv = reinterpret_cast<const float4*>(centers)[ci * (IN_F / 4) + tid];
        s_keys[base + 0] = __float_as_uint(cv.x);
        s_keys[base + 1] = __float_as_uint(cv.y);
        s_keys[base + 2] = __float_as_uint(cv.z);
        s_keys[base + 3] = __float_as_uint(cv.w);
    }
    __syncthreads();

    // radix-select threshold T = TOPK-th largest key
    unsigned prefix    = 0;
    int      remaining = TOPK;
#pragma unroll
    for (int p = 0; p < 4; p++) {
        const int shift = 24 - 8 * p;
#pragma unroll
        for (int j = 0; j < 4; j++) {
            unsigned key = s_keys[base + j];
            bool match = (p == 0) ||
                         ((key >> (shift + 8)) == (prefix >> (shift + 8)));
            if (match) atomicAdd(&s_hist[p][(key >> shift) & 255u], 1u);
        }
        __syncthreads();
        unsigned v = 0, cnt = 0;
        if (tid < 256) {
            cnt = s_hist[p][tid];
            v = cnt;
#pragma unroll
            for (int off = 1; off < 32; off <<= 1) {
                unsigned n = __shfl_down_sync(0xffffffffu, v, off);
                if (lane + off < 32) v += n;
            }
            if (lane == 0) s_wsum[wid] = v;
        }
        __syncthreads();
        if (tid < 256) {
            unsigned off = 0;
            for (int w2 = wid + 1; w2 < 8; w2++) off += s_wsum[w2];
            unsigned ge = v + off;           // #keys with byte >= tid (among matching)
            unsigned gt = ge - cnt;          // #keys with byte >  tid
            if ((int)ge >= remaining && (int)gt < remaining) {   // unique crossing bin
                s_ints[1] = remaining - (int)gt;
                s_ints[2] = (int)(prefix | ((unsigned)tid << shift));
            }
        }
        __syncthreads();
        remaining = s_ints[1];
        prefix    = (unsigned)s_ints[2];
        __syncthreads();
    }
    const unsigned T = prefix;
    const int      R = remaining;   // take the R lowest-index ties (jax top_k order)

    // tie-rank prefix scan (index order) + write masked x
    int cnt4[4];
    int tot = 0;
#pragma unroll
    for (int j = 0; j < 4; j++) {
        cnt4[j] = tot;
        tot += (s_keys[base + j] == T) ? 1 : 0;
    }
    int incl = tot;
#pragma unroll
    for (int off = 1; off < 32; off <<= 1) {
        int n = __shfl_up_sync(0xffffffffu, incl, off);
        if (lane >= off) incl += n;
    }
    if (lane == 31) s_warp[wid] = incl;
    __syncthreads();
    if (wid == 0) {
        int v = s_warp[lane];
#pragma unroll
        for (int off = 1; off < 32; off <<= 1) {
            int n = __shfl_up_sync(0xffffffffu, v, off);
            if (lane >= off) v += n;
        }
        s_warp[lane] = v;
    }
    __syncthreads();
    const int excl = incl - tot + (wid > 0 ? s_warp[wid - 1] : 0);
    const float xin[4] = { xv4.x, xv4.y, xv4.z, xv4.w };
    float o4[4];
#pragma unroll
    for (int j = 0; j < 4; j++) {
        unsigned key = s_keys[base + j];
        bool sel = (key > T) || (key == T && (excl + cnt4[j]) < R);
        o4[j] = sel ? xin[j] : 0.f;
    }
    reinterpret_cast<float4*>(g_xmask)[tid] = make_float4(o4[0], o4[1], o4[2], o4[3]);
}

// ---------------------------------------------------------------------------
// Kernel 4: out = W @ x_masked + bias. Persistent single-wave matvec:
// grid=888 (148 SMs x 6 blocks), block=256, warps stride rows by 7104.
// R3's dual same-row accumulator streams, natural register allocation.
// ---------------------------------------------------------------------------
#define MV_GRID   888
#define MV_WARPS  (MV_GRID * 8)   // 7104

__global__ void __launch_bounds__(256)
matvec_kernel(const float* __restrict__ W,
              const float* __restrict__ bias,
              float* __restrict__ out)
{
    __shared__ float4 sx[IN_F / 4];
    const int tid = threadIdx.x;
    for (int i = tid; i < IN_F / 4; i += 256)
        sx[i] = reinterpret_cast<const float4*>(g_xmask)[i];
    __syncthreads();

    const int warp = tid >> 5;
    const int lane = tid & 31;
    const int wg   = blockIdx.x * 8 + warp;   // 0 .. 7103

    for (int row = wg; row < OUT_F; row += MV_WARPS) {
        const float4* wr = reinterpret_cast<const float4*>(W + (size_t)row * IN_F);
        float acc0 = 0.f, acc1 = 0.f;
#pragma unroll 4
        for (int j = lane; j < IN_F / 4; j += 64) {
            float4 wa = wr[j];
            float4 wb = wr[j + 32];
            float4 xa = sx[j];
            float4 xb = sx[j + 32];
            acc0 += wa.x * xa.x + wa.y * xa.y + wa.z * xa.z + wa.w * xa.w;
            acc1 += wb.x * xb.x + wb.y * xb.y + wb.z * xb.z + wb.w * xb.w;
        }
        float acc = acc0 + acc1;
#pragma unroll
        for (int o = 16; o > 0; o >>= 1)
            acc += __shfl_xor_sync(0xffffffffu, acc, o);
        if (lane == 0)
            out[row] = acc + bias[row];
    }
}

// ---------------------------------------------------------------------------
extern "C" void kernel_launch(void* const* d_in, const int* in_sizes, int n_in,
                              void* d_out, int out_size)
{
    const float* x       = (const float*)d_in[0];  // [4096]
    const float* weight  = (const float*)d_in[1];  // [11008, 4096]
    const float* bias    = (const float*)d_in[2];  // [11008]
    const float* centers = (const float*)d_in[3];  // [16, 4096]
    float*       out     = (float*)d_out;          // [11008]

    softmax_kernel<<<1, 1024>>>(x);
    dist_kernel<<<NC, 1024>>>(centers);
    select_kernel<<<1, 1024>>>(x, centers);
    matvec_kernel<<<MV_GRID, 256>>>(weight, bias, out);
}